// round 2
// baseline (speedup 1.0000x reference)
#include <cuda_runtime.h>
#include <cstdint>

#define B_  32
#define C_  64
#define L_  16384
#define T_  128
#define NT  256

// Dynamic smem layout (float units):
//   [0,     8192)   xt[64][128]  x tile, later overwritten with deformed tile
//   [8192,  12288)  w1c[64][64]  offset conv weights, transposed [k][co]
//   [12288, 16384)  w2c[64][64]  regular conv weights, transposed [k][co]
//   [16384, 16448)  ob[64]       offset bias
//   [16448, 16512)  rb[64]       regular bias
#define SMEM_FLOATS 16512
#define SMEM_BYTES  (SMEM_FLOATS * 4)

__device__ __forceinline__ unsigned long long pk2(float lo, float hi) {
    unsigned long long r;
    asm("mov.b64 %0, {%1, %2};" : "=l"(r) : "f"(lo), "f"(hi));
    return r;
}
__device__ __forceinline__ void upk2(unsigned long long v, float& lo, float& hi) {
    asm("mov.b64 {%0, %1}, %2;" : "=f"(lo), "=f"(hi) : "l"(v));
}
__device__ __forceinline__ void fma2(unsigned long long& d, unsigned long long a, unsigned long long b) {
    asm("fma.rn.f32x2 %0, %1, %2, %0;" : "+l"(d) : "l"(a), "l"(b));
}

// One 64x(4x8) GEMM k-step: a = 4 weights (packed to pairs), b = 8 positions
// read as 4 packed f32x2 directly from smem (2x LDS.128). 16 FFMA2 per step.
#define MM_STEP(WPTR)                                                          \
    do {                                                                       \
        float4 a = *reinterpret_cast<const float4*>(&(WPTR)[(k << 6) + c0]);   \
        const ulonglong2* bp =                                                 \
            reinterpret_cast<const ulonglong2*>(&s_xt[k * T_ + lx]);           \
        ulonglong2 q0 = bp[0];                                                 \
        ulonglong2 q1 = bp[1];                                                 \
        unsigned long long a0 = pk2(a.x, a.x), a1 = pk2(a.y, a.y);             \
        unsigned long long a2 = pk2(a.z, a.z), a3 = pk2(a.w, a.w);             \
        fma2(acc[0][0], a0, q0.x); fma2(acc[0][1], a0, q0.y);                  \
        fma2(acc[0][2], a0, q1.x); fma2(acc[0][3], a0, q1.y);                  \
        fma2(acc[1][0], a1, q0.x); fma2(acc[1][1], a1, q0.y);                  \
        fma2(acc[1][2], a1, q1.x); fma2(acc[1][3], a1, q1.y);                  \
        fma2(acc[2][0], a2, q0.x); fma2(acc[2][1], a2, q0.y);                  \
        fma2(acc[2][2], a2, q1.x); fma2(acc[2][3], a2, q1.y);                  \
        fma2(acc[3][0], a3, q0.x); fma2(acc[3][1], a3, q0.y);                  \
        fma2(acc[3][2], a3, q1.x); fma2(acc[3][3], a3, q1.y);                  \
    } while (0)

__global__ void __launch_bounds__(NT, 2)
deform_conv1d_kernel(const float* __restrict__ x,
                     const float* __restrict__ w1, const float* __restrict__ b1,
                     const float* __restrict__ w2, const float* __restrict__ b2,
                     float* __restrict__ out)
{
    extern __shared__ float smem[];
    float* s_xt  = smem;            // [64][128]
    float* s_w1c = smem + 8192;     // [k][co]
    float* s_w2c = smem + 12288;    // [k][co]
    float* s_ob  = smem + 16384;
    float* s_rb  = smem + 16448;

    const int b   = blockIdx.y;
    const int l0  = blockIdx.x * T_;
    const int tid = threadIdx.x;

    // Load weights transposed: w[co][k] -> wc[k][co]
    for (int i = tid; i < C_ * C_; i += NT) {
        int co = i >> 6, k = i & 63;
        s_w1c[(k << 6) + co] = w1[i];
        s_w2c[(k << 6) + co] = w2[i];
    }
    if (tid < C_) { s_ob[tid] = b1[tid]; s_rb[tid] = b2[tid]; }

    // Load x tile [64 channels][128 positions], vectorized + coalesced.
    const float* xb = x + (size_t)b * (size_t)(C_ * L_);
    for (int i = tid; i < C_ * (T_ / 4); i += NT) {
        int c  = i >> 5;        // T_/4 = 32
        int l4 = i & 31;
        float4 v = *reinterpret_cast<const float4*>(xb + (size_t)c * L_ + l0 + (l4 << 2));
        *reinterpret_cast<float4*>(&s_xt[c * T_ + (l4 << 2)]) = v;
    }
    __syncthreads();

    const int ty = tid >> 4;        // 0..15 -> channel group
    const int tx = tid & 15;        // 0..15 -> position group
    const int c0 = ty << 2;         // 4 channels per thread
    const int lx = tx << 3;         // 8 positions per thread

    // ---------------- matmul 1: offsets = W1 . x ----------------
    unsigned long long acc[4][4];
    #pragma unroll
    for (int i = 0; i < 4; i++)
        #pragma unroll
        for (int j = 0; j < 4; j++) acc[i][j] = 0ull;

    #pragma unroll 8
    for (int k = 0; k < C_; k++) { MM_STEP(s_w1c); }

    __syncthreads();   // everyone done reading x tile; safe to overwrite

    // ---------------- gather + bilinear interpolation ----------------
    #pragma unroll
    for (int i = 0; i < 4; i++) {
        const int c = c0 + i;
        const float* row = xb + (size_t)c * L_;
        const float bias = s_ob[c];
        #pragma unroll
        for (int j = 0; j < 4; j++) {
            float o0, o1;
            upk2(acc[i][j], o0, o1);
            {
                const int lg = l0 + lx + (j << 1);
                float pos = fminf(fmaxf((float)lg + (o0 + bias), 0.0f), (float)(L_ - 1));
                float fl  = floorf(pos);
                float fr  = pos - fl;
                int i0 = (int)fl;
                int i1 = min(i0 + 1, L_ - 1);
                float v0 = __ldg(row + i0), v1 = __ldg(row + i1);
                s_xt[c * T_ + lx + (j << 1)] = (1.0f - fr) * v0 + fr * v1;
            }
            {
                const int lg = l0 + lx + (j << 1) + 1;
                float pos = fminf(fmaxf((float)lg + (o1 + bias), 0.0f), (float)(L_ - 1));
                float fl  = floorf(pos);
                float fr  = pos - fl;
                int i0 = (int)fl;
                int i1 = min(i0 + 1, L_ - 1);
                float v0 = __ldg(row + i0), v1 = __ldg(row + i1);
                s_xt[c * T_ + lx + (j << 1) + 1] = (1.0f - fr) * v0 + fr * v1;
            }
        }
    }
    __syncthreads();

    // ---------------- matmul 2: out = W2 . x_deform ----------------
    #pragma unroll
    for (int i = 0; i < 4; i++)
        #pragma unroll
        for (int j = 0; j < 4; j++) acc[i][j] = 0ull;

    #pragma unroll 8
    for (int k = 0; k < C_; k++) { MM_STEP(s_w2c); }

    // Epilogue: unpack, add bias, vectorized store.
    float* ob_ = out + (size_t)b * (size_t)(C_ * L_);
    #pragma unroll
    for (int i = 0; i < 4; i++) {
        const int co = c0 + i;
        const float bias = s_rb[co];
        float r0, r1, r2, r3, r4, r5, r6, r7;
        upk2(acc[i][0], r0, r1);
        upk2(acc[i][1], r2, r3);
        upk2(acc[i][2], r4, r5);
        upk2(acc[i][3], r6, r7);
        float* dst = ob_ + (size_t)co * L_ + l0 + lx;
        *reinterpret_cast<float4*>(dst)     = make_float4(r0 + bias, r1 + bias, r2 + bias, r3 + bias);
        *reinterpret_cast<float4*>(dst + 4) = make_float4(r4 + bias, r5 + bias, r6 + bias, r7 + bias);
    }
}

extern "C" void kernel_launch(void* const* d_in, const int* in_sizes, int n_in,
                              void* d_out, int out_size)
{
    (void)in_sizes; (void)n_in; (void)out_size;
    const float* x  = (const float*)d_in[0];
    const float* w1 = (const float*)d_in[1];
    const float* b1 = (const float*)d_in[2];
    const float* w2 = (const float*)d_in[3];
    const float* b2 = (const float*)d_in[4];
    float* out = (float*)d_out;

    cudaFuncSetAttribute(deform_conv1d_kernel,
                         cudaFuncAttributeMaxDynamicSharedMemorySize, SMEM_BYTES);

    dim3 grid(L_ / T_, B_);   // 128 x 32 = 4096 blocks
    deform_conv1d_kernel<<<grid, NT, SMEM_BYTES>>>(x, w1, b1, w2, b2, out);
}

// round 5
// speedup vs baseline: 1.0941x; 1.0941x over previous
#include <cuda_runtime.h>
#include <cstdint>

#define B_  32
#define C_  64
#define L_  16384
#define T_  128
#define NT  128

// Dynamic smem layout (float units):
//   [0,     8192)   xt[64][128]   x tile, later overwritten with deformed tile
//   [8192,  16384)  w1d[64][128]  offset weights, transposed + DUPLICATED: [k][2*co{+0,+1} same value]
//   [16384, 24576)  w2d[64][128]  regular weights, transposed + duplicated
//   [24576, 24640)  ob[64]        offset bias
//   [24640, 24704)  rb[64]        regular bias
#define SMEM_FLOATS 24704
#define SMEM_BYTES  (SMEM_FLOATS * 4)

__device__ __forceinline__ unsigned long long pk2(float lo, float hi) {
    unsigned long long r;
    asm("mov.b64 %0, {%1, %2};" : "=l"(r) : "f"(lo), "f"(hi));
    return r;
}
__device__ __forceinline__ void upk2(unsigned long long v, float& lo, float& hi) {
    asm("mov.b64 {%0, %1}, %2;" : "=f"(lo), "=f"(hi) : "l"(v));
}
__device__ __forceinline__ void fma2(unsigned long long& d, unsigned long long a, unsigned long long b) {
    asm("fma.rn.f32x2 %0, %1, %2, %0;" : "+l"(d) : "l"(a), "l"(b));
}

// One k-step of a 64x(8x8) register-tiled GEMM.
// Weights come out of smem ALREADY duplicated as packed (w,w) f32x2 pairs:
// 4x LDS.128 (broadcast across tx lanes -> 1 wavefront each).
// xt: 2x LDS.128 (8 positions -> 4 packed f32x2).
// 32x FFMA2 = 64 FMA. No MOVs.
#define MM_STEP8(WD)                                                           \
    do {                                                                       \
        const ulonglong2* wp =                                                 \
            reinterpret_cast<const ulonglong2*>(&(WD)[(k << 7) + (c0 << 1)]);  \
        ulonglong2 wA = wp[0], wB = wp[1], wC = wp[2], wD = wp[3];             \
        const ulonglong2* bp =                                                 \
            reinterpret_cast<const ulonglong2*>(&s_xt[(k << 7) + lx]);         \
        ulonglong2 q0 = bp[0], q1 = bp[1];                                     \
        fma2(acc[0][0], wA.x, q0.x); fma2(acc[0][1], wA.x, q0.y);              \
        fma2(acc[0][2], wA.x, q1.x); fma2(acc[0][3], wA.x, q1.y);              \
        fma2(acc[1][0], wA.y, q0.x); fma2(acc[1][1], wA.y, q0.y);              \
        fma2(acc[1][2], wA.y, q1.x); fma2(acc[1][3], wA.y, q1.y);              \
        fma2(acc[2][0], wB.x, q0.x); fma2(acc[2][1], wB.x, q0.y);              \
        fma2(acc[2][2], wB.x, q1.x); fma2(acc[2][3], wB.x, q1.y);              \
        fma2(acc[3][0], wB.y, q0.x); fma2(acc[3][1], wB.y, q0.y);              \
        fma2(acc[3][2], wB.y, q1.x); fma2(acc[3][3], wB.y, q1.y);              \
        fma2(acc[4][0], wC.x, q0.x); fma2(acc[4][1], wC.x, q0.y);              \
        fma2(acc[4][2], wC.x, q1.x); fma2(acc[4][3], wC.x, q1.y);              \
        fma2(acc[5][0], wC.y, q0.x); fma2(acc[5][1], wC.y, q0.y);              \
        fma2(acc[5][2], wC.y, q1.x); fma2(acc[5][3], wC.y, q1.y);              \
        fma2(acc[6][0], wD.x, q0.x); fma2(acc[6][1], wD.x, q0.y);              \
        fma2(acc[6][2], wD.x, q1.x); fma2(acc[6][3], wD.x, q1.y);              \
        fma2(acc[7][0], wD.y, q0.x); fma2(acc[7][1], wD.y, q0.y);              \
        fma2(acc[7][2], wD.y, q1.x); fma2(acc[7][3], wD.y, q1.y);              \
    } while (0)

__global__ void __launch_bounds__(NT, 2)
deform_conv1d_kernel(const float* __restrict__ x,
                     const float* __restrict__ w1, const float* __restrict__ b1,
                     const float* __restrict__ w2, const float* __restrict__ b2,
                     float* __restrict__ out)
{
    extern __shared__ float smem[];
    float* s_xt  = smem;            // [64][128]
    float* s_w1d = smem + 8192;     // [k][2*co] duplicated
    float* s_w2d = smem + 16384;    // [k][2*co] duplicated
    float* s_ob  = smem + 24576;
    float* s_rb  = smem + 24640;

    const int b   = blockIdx.y;
    const int l0  = blockIdx.x * T_;
    const int tid = threadIdx.x;

    // Weights transposed + duplicated: w[co][k] -> wd[k][2*co] = wd[k][2*co+1]
    for (int i = tid; i < C_ * C_; i += NT) {
        int co = i >> 6, k = i & 63;
        float v1 = w1[i], v2 = w2[i];
        int base = (k << 7) + (co << 1);
        s_w1d[base] = v1; s_w1d[base + 1] = v1;
        s_w2d[base] = v2; s_w2d[base + 1] = v2;
    }
    if (tid < C_) { s_ob[tid] = b1[tid]; s_rb[tid] = b2[tid]; }

    // Load x tile [64 channels][128 positions], vectorized + coalesced.
    const float* xb = x + (size_t)b * (size_t)(C_ * L_);
    for (int i = tid; i < C_ * (T_ / 4); i += NT) {
        int c  = i >> 5;        // T_/4 = 32
        int l4 = i & 31;
        float4 v = *reinterpret_cast<const float4*>(xb + (size_t)c * L_ + l0 + (l4 << 2));
        *reinterpret_cast<float4*>(&s_xt[(c << 7) + (l4 << 2)]) = v;
    }
    __syncthreads();

    const int ty = tid >> 4;        // 0..7  -> channel group
    const int tx = tid & 15;        // 0..15 -> position group
    const int c0 = ty << 3;         // 8 channels per thread
    const int lx = tx << 3;         // 8 positions per thread

    // ---------------- matmul 1: offsets = W1 . x + b1 ----------------
    unsigned long long acc[8][4];
    #pragma unroll
    for (int i = 0; i < 8; i++) {
        float ob0 = s_ob[c0 + i];
        unsigned long long p = pk2(ob0, ob0);
        #pragma unroll
        for (int j = 0; j < 4; j++) acc[i][j] = p;   // bias pre-loaded
    }

    #pragma unroll 4
    for (int k = 0; k < C_; k++) { MM_STEP8(s_w1d); }

    __syncthreads();   // everyone done reading x tile; safe to overwrite

    // ---------------- gather + linear interpolation ----------------
    #pragma unroll
    for (int i = 0; i < 8; i++) {
        const int c = c0 + i;
        const float* row = xb + (size_t)c * L_;
        #pragma unroll
        for (int j = 0; j < 4; j++) {
            float o0, o1;
            upk2(acc[i][j], o0, o1);   // already includes bias
            const int lg = l0 + lx + (j << 1);

            float pos0 = fminf(fmaxf((float)lg + o0, 0.0f), (float)(L_ - 1));
            float fl0  = floorf(pos0);
            float fr0  = pos0 - fl0;
            int i00 = (int)fl0;
            int i01 = min(i00 + 1, L_ - 1);
            float a0 = __ldg(row + i00), b0v = __ldg(row + i01);
            float d0 = (1.0f - fr0) * a0 + fr0 * b0v;

            float pos1 = fminf(fmaxf((float)(lg + 1) + o1, 0.0f), (float)(L_ - 1));
            float fl1  = floorf(pos1);
            float fr1  = pos1 - fl1;
            int i10 = (int)fl1;
            int i11 = min(i10 + 1, L_ - 1);
            float a1 = __ldg(row + i10), b1v = __ldg(row + i11);
            float d1 = (1.0f - fr1) * a1 + fr1 * b1v;

            *reinterpret_cast<unsigned long long*>(&s_xt[(c << 7) + lx + (j << 1)]) = pk2(d0, d1);
        }
    }
    __syncthreads();

    // ---------------- matmul 2: out = W2 . x_deform + b2 ----------------
    #pragma unroll
    for (int i = 0; i < 8; i++) {
        float rb0 = s_rb[c0 + i];
        unsigned long long p = pk2(rb0, rb0);
        #pragma unroll
        for (int j = 0; j < 4; j++) acc[i][j] = p;   // bias pre-loaded
    }

    #pragma unroll 4
    for (int k = 0; k < C_; k++) { MM_STEP8(s_w2d); }

    // Epilogue: unpack + vectorized store (bias already in acc).
    float* ob_ = out + (size_t)b * (size_t)(C_ * L_);
    #pragma unroll
    for (int i = 0; i < 8; i++) {
        const int co = c0 + i;
        float r0, r1, r2, r3, r4, r5, r6, r7;
        upk2(acc[i][0], r0, r1);
        upk2(acc[i][1], r2, r3);
        upk2(acc[i][2], r4, r5);
        upk2(acc[i][3], r6, r7);
        float* dst = ob_ + (size_t)co * L_ + l0 + lx;
        *reinterpret_cast<float4*>(dst)     = make_float4(r0, r1, r2, r3);
        *reinterpret_cast<float4*>(dst + 4) = make_float4(r4, r5, r6, r7);
    }
}

extern "C" void kernel_launch(void* const* d_in, const int* in_sizes, int n_in,
                              void* d_out, int out_size)
{
    (void)in_sizes; (void)n_in; (void)out_size;
    const float* x  = (const float*)d_in[0];
    const float* w1 = (const float*)d_in[1];
    const float* b1 = (const float*)d_in[2];
    const float* w2 = (const float*)d_in[3];
    const float* b2 = (const float*)d_in[4];
    float* out = (float*)d_out;

    cudaFuncSetAttribute(deform_conv1d_kernel,
                         cudaFuncAttributeMaxDynamicSharedMemorySize, SMEM_BYTES);

    dim3 grid(L_ / T_, B_);   // 128 x 32 = 4096 blocks
    deform_conv1d_kernel<<<grid, NT, SMEM_BYTES>>>(x, w1, b1, w2, b2, out);
}

// round 6
// speedup vs baseline: 1.4915x; 1.3632x over previous
#include <cuda_runtime.h>
#include <cstdint>

#define B_  32
#define C_  64
#define L_  16384
#define T_  128
#define NT  128
#define H_  16
#define SX  160                 // haloed x row stride (floats)

// smem: s_xh[64][160] (40KB) + s_od[64][128] (32KB) = 73728 B -> 2 blocks/SM
#define SMEM_BYTES ((C_ * SX + C_ * T_) * 4)

// Weights transposed + duplicated, staged once by a prologue kernel:
// g_wXd[ci][2*co] == g_wXd[ci][2*co+1] == w[co][ci].  64KB total, L1-resident.
__device__ float g_w1d[C_ * 2 * C_];
__device__ float g_w2d[C_ * 2 * C_];

__global__ void transpose_dup_kernel(const float* __restrict__ w1,
                                     const float* __restrict__ w2)
{
    int i = blockIdx.x * blockDim.x + threadIdx.x;
    if (i < C_ * C_) {
        int co = i >> 6, ci = i & 63;
        float v1 = w1[i], v2 = w2[i];
        g_w1d[ci * 128 + 2 * co] = v1; g_w1d[ci * 128 + 2 * co + 1] = v1;
        g_w2d[ci * 128 + 2 * co] = v2; g_w2d[ci * 128 + 2 * co + 1] = v2;
    }
}

__device__ __forceinline__ unsigned long long pk2(float lo, float hi) {
    unsigned long long r;
    asm("mov.b64 %0, {%1, %2};" : "=l"(r) : "f"(lo), "f"(hi));
    return r;
}
__device__ __forceinline__ void upk2(unsigned long long v, float& lo, float& hi) {
    asm("mov.b64 {%0, %1}, %2;" : "=f"(lo), "=f"(hi) : "l"(v));
}
__device__ __forceinline__ void fma2(unsigned long long& d, unsigned long long a, unsigned long long b) {
    asm("fma.rn.f32x2 %0, %1, %2, %0;" : "+l"(d) : "l"(a), "l"(b));
}

// One k-step: weights via 4x broadcast LDG.128 (pre-duplicated pairs, L1-hot),
// x via 2x LDS.128 (contiguous 128B per instruction -> 1 wavefront each),
// 32x FFMA2. Zero MOVs.
#define MM_STEP(WD, XBASE, XSTRIDE)                                            \
    do {                                                                       \
        const ulonglong2* wp =                                                 \
            reinterpret_cast<const ulonglong2*>(&(WD)[(k << 7) + (c0 << 1)]);  \
        ulonglong2 w0 = wp[0], w1r = wp[1], w2r = wp[2], w3r = wp[3];          \
        const float* xr = (XBASE) + k * (XSTRIDE);                             \
        ulonglong2 qa = *reinterpret_cast<const ulonglong2*>(xr + pA);         \
        ulonglong2 qb = *reinterpret_cast<const ulonglong2*>(xr + pB);         \
        fma2(acc[0][0], w0.x, qa.x);  fma2(acc[0][1], w0.x, qa.y);             \
        fma2(acc[0][2], w0.x, qb.x);  fma2(acc[0][3], w0.x, qb.y);             \
        fma2(acc[1][0], w0.y, qa.x);  fma2(acc[1][1], w0.y, qa.y);             \
        fma2(acc[1][2], w0.y, qb.x);  fma2(acc[1][3], w0.y, qb.y);             \
        fma2(acc[2][0], w1r.x, qa.x); fma2(acc[2][1], w1r.x, qa.y);            \
        fma2(acc[2][2], w1r.x, qb.x); fma2(acc[2][3], w1r.x, qb.y);            \
        fma2(acc[3][0], w1r.y, qa.x); fma2(acc[3][1], w1r.y, qa.y);            \
        fma2(acc[3][2], w1r.y, qb.x); fma2(acc[3][3], w1r.y, qb.y);            \
        fma2(acc[4][0], w2r.x, qa.x); fma2(acc[4][1], w2r.x, qa.y);            \
        fma2(acc[4][2], w2r.x, qb.x); fma2(acc[4][3], w2r.x, qb.y);            \
        fma2(acc[5][0], w2r.y, qa.x); fma2(acc[5][1], w2r.y, qa.y);            \
        fma2(acc[5][2], w2r.y, qb.x); fma2(acc[5][3], w2r.y, qb.y);            \
        fma2(acc[6][0], w3r.x, qa.x); fma2(acc[6][1], w3r.x, qa.y);            \
        fma2(acc[6][2], w3r.x, qb.x); fma2(acc[6][3], w3r.x, qb.y);            \
        fma2(acc[7][0], w3r.y, qa.x); fma2(acc[7][1], w3r.y, qa.y);            \
        fma2(acc[7][2], w3r.y, qb.x); fma2(acc[7][3], w3r.y, qb.y);            \
    } while (0)

__global__ void __launch_bounds__(NT, 2)
deform_conv1d_kernel(const float* __restrict__ x,
                     const float* __restrict__ b1v,
                     const float* __restrict__ b2v,
                     float* __restrict__ out)
{
    extern __shared__ float sm[];
    float* s_xh = sm;                 // [64][160] haloed x tile
    float* s_od = sm + C_ * SX;       // [64][128] offsets, then deformed tile

    const int b   = blockIdx.y;
    const int l0  = blockIdx.x * T_;
    const int tid = threadIdx.x;
    const float* xb = x + (size_t)b * (size_t)(C_ * L_);

    // ---- load haloed x tile [64][160] covering positions [l0-16, l0+144) ----
    if (blockIdx.x != 0 && blockIdx.x != gridDim.x - 1) {
        #pragma unroll 4
        for (int i = tid; i < C_ * (SX / 4); i += NT) {
            int c = i / (SX / 4), j = i - c * (SX / 4);
            float4 v = *reinterpret_cast<const float4*>(xb + (size_t)c * L_ + (l0 - H_) + (j << 2));
            *reinterpret_cast<float4*>(&s_xh[c * SX + (j << 2)]) = v;
        }
    } else {
        for (int i = tid; i < C_ * SX; i += NT) {
            int c = i / SX, j = i - c * SX;
            int g = min(max(l0 - H_ + j, 0), L_ - 1);
            s_xh[c * SX + j] = xb[(size_t)c * L_ + g];
        }
    }
    __syncthreads();

    // GEMM mapping: warp = chhalf(2) x poshalf(2); lane = cg(4) x pg(8).
    // Thread tile: 8 channels x (quad A + quad B) = 8x8.
    const int warp = tid >> 5, lane = tid & 31;
    const int chh = warp >> 1, phh = warp & 1;
    const int cg = lane >> 3, pg = lane & 7;
    const int c0 = (chh << 5) + (cg << 3);          // 8 channels c0..c0+7
    const int pA = (phh << 6) + (pg << 2);          // quad A
    const int pB = pA + 32;                         // quad B

    // ---------------- GEMM1: offsets = W1.x + b1 ----------------
    unsigned long long acc[8][4];
    #pragma unroll
    for (int i = 0; i < 8; i++) {
        float bv = __ldg(b1v + c0 + i);
        unsigned long long p = pk2(bv, bv);
        #pragma unroll
        for (int j = 0; j < 4; j++) acc[i][j] = p;
    }
    #pragma unroll 2
    for (int k = 0; k < C_; k++) { MM_STEP(g_w1d, s_xh + H_, SX); }

    // store offsets to s_od (no sync needed: s_od untouched so far)
    #pragma unroll
    for (int i = 0; i < 8; i++) {
        float* dst = &s_od[(c0 + i) * T_];
        *reinterpret_cast<ulonglong2*>(dst + pA) = make_ulonglong2(acc[i][0], acc[i][1]);
        *reinterpret_cast<ulonglong2*>(dst + pB) = make_ulonglong2(acc[i][2], acc[i][3]);
    }
    __syncthreads();

    // ---------------- gather: warp-consecutive positions, smem-resident ----------------
    const int wl = (warp << 5) + lane;              // 0..127
    const float basef = (float)(l0 + wl);
    #pragma unroll 2
    for (int c = 0; c < C_; c++) {
        float off  = s_od[c * T_ + wl];
        float posf = fminf(fmaxf(basef + off, 0.0f), (float)(L_ - 1));
        float fl   = floorf(posf);
        float fr   = posf - fl;
        int   i0   = (int)fl;
        int   h    = i0 - l0 + H_;
        float v0, v1;
        if (h >= 0 && h <= SX - 2) {                // |offset| < 15: always
            v0 = s_xh[c * SX + h];
            v1 = s_xh[c * SX + h + 1];
        } else {                                    // ultra-rare fallback
            const float* row = xb + (size_t)c * L_;
            v0 = __ldg(row + i0);
            v1 = __ldg(row + min(i0 + 1, L_ - 1));
        }
        s_od[c * T_ + wl] = (1.0f - fr) * v0 + fr * v1;   // own slot: no race
    }
    __syncthreads();

    // ---------------- GEMM2: out = W2.x_deform + b2 ----------------
    #pragma unroll
    for (int i = 0; i < 8; i++) {
        float bv = __ldg(b2v + c0 + i);
        unsigned long long p = pk2(bv, bv);
        #pragma unroll
        for (int j = 0; j < 4; j++) acc[i][j] = p;
    }
    #pragma unroll 2
    for (int k = 0; k < C_; k++) { MM_STEP(g_w2d, s_od, T_); }

    // epilogue: coalesced float4 stores
    float* ob = out + (size_t)b * (size_t)(C_ * L_) + l0;
    #pragma unroll
    for (int i = 0; i < 8; i++) {
        float r0, r1, r2, r3;
        float* dst = ob + (size_t)(c0 + i) * L_;
        upk2(acc[i][0], r0, r1); upk2(acc[i][1], r2, r3);
        *reinterpret_cast<float4*>(dst + pA) = make_float4(r0, r1, r2, r3);
        upk2(acc[i][2], r0, r1); upk2(acc[i][3], r2, r3);
        *reinterpret_cast<float4*>(dst + pB) = make_float4(r0, r1, r2, r3);
    }
}

extern "C" void kernel_launch(void* const* d_in, const int* in_sizes, int n_in,
                              void* d_out, int out_size)
{
    (void)in_sizes; (void)n_in; (void)out_size;
    const float* x  = (const float*)d_in[0];
    const float* w1 = (const float*)d_in[1];
    const float* b1 = (const float*)d_in[2];
    const float* w2 = (const float*)d_in[3];
    const float* b2 = (const float*)d_in[4];
    float* out = (float*)d_out;

    transpose_dup_kernel<<<(C_ * C_ + 255) / 256, 256>>>(w1, w2);

    cudaFuncSetAttribute(deform_conv1d_kernel,
                         cudaFuncAttributeMaxDynamicSharedMemorySize, SMEM_BYTES);
    dim3 grid(L_ / T_, B_);
    deform_conv1d_kernel<<<grid, NT, SMEM_BYTES>>>(x, b1, b2, out);
}

// round 10
// speedup vs baseline: 2.5392x; 1.7025x over previous
#include <cuda_runtime.h>
#include <cuda_bf16.h>
#include <cstdint>

#define B_  32
#define C_  64
#define L_  16384
#define T_  128
#define NT  128
#define H_  16
#define SXP 164     // haloed row stride: 164 mod 32 = 4 -> column LDS conflict-free

// Precomputed B fragments (weights in exact mma.sync B-fragment layout).
// [kcD(8: 0-3 = w_hi chunks, 4-7 = w_lo chunks)][nt(8)][lane(32)] -> uint2 {b0,b1}
__device__ __align__(16) uint2 g_Bf1[8 * 8 * 32];
__device__ __align__(16) uint2 g_Bf2[8 * 8 * 32];

// ---- bf16 split helpers: hi = truncation (prmt), lo = rn(f - hi) ----
__device__ __forceinline__ uint32_t pack_hi(float f0, float f1) {
    uint32_t r;
    asm("prmt.b32 %0, %1, %2, 0x7632;"
        : "=r"(r) : "r"(__float_as_uint(f0)), "r"(__float_as_uint(f1)));
    return r;                     // {lo16 = hi16(f0), hi16 = hi16(f1)}
}
__device__ __forceinline__ uint32_t pack_lo(float f0, float f1) {
    float h0 = __uint_as_float(__float_as_uint(f0) & 0xFFFF0000u);
    float h1 = __uint_as_float(__float_as_uint(f1) & 0xFFFF0000u);
    float l0 = f0 - h0, l1 = f1 - h1;
    uint32_t d;
    asm("cvt.rn.bf16x2.f32 %0, %1, %2;" : "=r"(d) : "f"(l1), "f"(l0));
    return d;                     // {lo16 = bf16(l0), hi16 = bf16(l1)}
}

// ---- prologue: build B fragments for both weight matrices ----
__global__ void build_frags_kernel(const float* __restrict__ w1,
                                   const float* __restrict__ w2)
{
    int i = blockIdx.x * blockDim.x + threadIdx.x;
    if (i >= 8 * 8 * 32) return;
    int lane = i & 31, nt = (i >> 5) & 7, kcD = i >> 8;
    int q = lane & 3, trow = lane >> 2;
    int co = nt * 8 + trow;
    int cb = (kcD & 3) * 16 + 2 * q;
    bool lo = (kcD >= 4);

    float f0 = w1[co * 64 + cb],     f1 = w1[co * 64 + cb + 1];
    float f2 = w1[co * 64 + cb + 8], f3 = w1[co * 64 + cb + 9];
    g_Bf1[i] = lo ? make_uint2(pack_lo(f0, f1), pack_lo(f2, f3))
                  : make_uint2(pack_hi(f0, f1), pack_hi(f2, f3));

    f0 = w2[co * 64 + cb];     f1 = w2[co * 64 + cb + 1];
    f2 = w2[co * 64 + cb + 8]; f3 = w2[co * 64 + cb + 9];
    g_Bf2[i] = lo ? make_uint2(pack_lo(f0, f1), pack_lo(f2, f3))
                  : make_uint2(pack_hi(f0, f1), pack_hi(f2, f3));
}

#define MMA16816(c, a, b0, b1)                                                 \
    asm volatile("mma.sync.aligned.m16n8k16.row.col.f32.bf16.bf16.f32 "        \
        "{%0,%1,%2,%3}, {%4,%5,%6,%7}, {%8,%9}, {%0,%1,%2,%3};"                \
        : "+f"((c)[0]), "+f"((c)[1]), "+f"((c)[2]), "+f"((c)[3])               \
        : "r"((a)[0]), "r"((a)[1]), "r"((a)[2]), "r"((a)[3]),                  \
          "r"(b0), "r"(b1))

// K layout (12 chunks of 16): kc 0-3 A=hi B=hi; 4-7 A=lo B=hi; 8-11 A=hi B=lo.
#define RUN_GEMM(GBF)                                                          \
    _Pragma("unroll")                                                          \
    for (int kc = 0; kc < 12; kc++) {                                          \
        const int kcD = (kc < 4) ? kc : kc - 4;                                \
        const uint32_t* a0 = (kc < 4) ? ahi[0][kc]                             \
                           : (kc < 8) ? alo[0][kc - 4] : ahi[0][kc - 8];       \
        const uint32_t* a1 = (kc < 4) ? ahi[1][kc]                             \
                           : (kc < 8) ? alo[1][kc - 4] : ahi[1][kc - 8];       \
        const uint2* bp = (GBF) + kcD * 256 + lane;                            \
        _Pragma("unroll")                                                      \
        for (int nt = 0; nt < 8; nt++) {                                       \
            uint2 bb = __ldg(bp + nt * 32);                                    \
            MMA16816(acc[0][nt], a0, bb.x, bb.y);                              \
            MMA16816(acc[1][nt], a1, bb.x, bb.y);                              \
        }                                                                      \
    }

__global__ void __launch_bounds__(NT, 2)
deform_conv1d_kernel(const float* __restrict__ x,
                     const float* __restrict__ b1v,
                     const float* __restrict__ b2v,
                     float* __restrict__ out)
{
    __shared__ __align__(16) float s_xh[C_ * SXP];   // 41984 B

    const int b   = blockIdx.y;
    const int l0  = blockIdx.x * T_;
    const int tid = threadIdx.x;
    const float* xb = x + (size_t)b * (size_t)(C_ * L_);

    // ---- haloed x tile [64][164] covering [l0-16, l0+148) ----
    if (blockIdx.x != 0 && blockIdx.x != gridDim.x - 1) {
        #pragma unroll 4
        for (int i = tid; i < C_ * (SXP / 4); i += NT) {
            int c = i / (SXP / 4), j = i - c * (SXP / 4);
            float4 v = *reinterpret_cast<const float4*>(
                xb + (size_t)c * L_ + (l0 - H_) + (j << 2));
            *reinterpret_cast<float4*>(&s_xh[c * SXP + (j << 2)]) = v;
        }
    } else {
        for (int i = tid; i < C_ * SXP; i += NT) {
            int c = i / SXP, j = i - c * SXP;
            int g = min(max(l0 - H_ + j, 0), L_ - 1);
            s_xh[c * SXP + j] = xb[(size_t)c * L_ + g];
        }
    }
    __syncthreads();        // the only block-wide sync

    const int lane = tid & 31, warp = tid >> 5;
    const int q = lane & 3, trow = lane >> 2;
    const int r = warp * 32 + trow;     // base tile row; thread rows r+{0,8,16,24}

    // ---- build A1 fragments from x tile (hi/lo split) ----
    // ahi[mt][kc][j]: j0=(row r(+16mt), cols cb..cb+1), j1=(row+8, cb),
    //                 j2=(row, cb+8), j3=(row+8, cb+8);  cb = 16kc+2q
    uint32_t ahi[2][4][4], alo[2][4][4];
    #pragma unroll
    for (int pi = 0; pi < 4; pi++) {
        const int p  = r + 8 * pi + H_;     // smem column index
        const int mt = pi >> 1, jr = pi & 1;
        #pragma unroll
        for (int kc = 0; kc < 4; kc++) {
            const int cb = kc * 16 + 2 * q;
            float f0 = s_xh[cb * SXP + p],       f1 = s_xh[(cb + 1) * SXP + p];
            float f2 = s_xh[(cb + 8) * SXP + p], f3 = s_xh[(cb + 9) * SXP + p];
            ahi[mt][kc][jr]     = pack_hi(f0, f1);
            alo[mt][kc][jr]     = pack_lo(f0, f1);
            ahi[mt][kc][2 + jr] = pack_hi(f2, f3);
            alo[mt][kc][2 + jr] = pack_lo(f2, f3);
        }
    }

    // ---- GEMM1: offsets[pos][ch] (bias added below) ----
    float acc[2][8][4];
    #pragma unroll
    for (int mt = 0; mt < 2; mt++)
        #pragma unroll
        for (int nt = 0; nt < 8; nt++)
            #pragma unroll
            for (int j = 0; j < 4; j++) acc[mt][nt][j] = 0.f;

    RUN_GEMM(g_Bf1);

    // ---- in-register gather: D1 fragment -> A2 fragment (same ownership map) ----
    const float2* b1p = reinterpret_cast<const float2*>(b1v);
    #pragma unroll
    for (int mt = 0; mt < 2; mt++) {
        #pragma unroll
        for (int kc = 0; kc < 4; kc++) {
            #pragma unroll
            for (int h2 = 0; h2 < 2; h2++) {
                const int nt  = 2 * kc + h2;
                const float2 bias = __ldg(b1p + nt * 4 + q);
                const int ch0 = nt * 8 + 2 * q;
                const int p0  = l0 + r + 16 * mt;   // global pos, row r
                float dv[4];
                #pragma unroll
                for (int e = 0; e < 4; e++) {       // e: {row0,ch0},{row0,ch1},{row1,ch0},{row1,ch1}
                    const int   ch   = ch0 + (e & 1);
                    const int   gpos = p0 + (e >> 1) * 8;
                    const float off  = acc[mt][nt][((e >> 1) << 1) | (e & 1)]
                                     + ((e & 1) ? bias.y : bias.x);
                    float posf = fminf(fmaxf((float)gpos + off, 0.0f), (float)(L_ - 1));
                    float fl   = floorf(posf);
                    float fr   = posf - fl;
                    int   i0   = (int)fl;
                    int   h    = i0 - l0 + H_;
                    float v0, v1;
                    if ((unsigned)h <= (unsigned)(SXP - 2)) {
                        v0 = s_xh[ch * SXP + h];
                        v1 = s_xh[ch * SXP + h + 1];
                    } else {                         // rare out-of-halo fallback
                        const float* row = xb + (size_t)ch * L_;
                        v0 = __ldg(row + i0);
                        v1 = __ldg(row + min(i0 + 1, L_ - 1));
                    }
                    dv[e] = (1.0f - fr) * v0 + fr * v1;
                }
                ahi[mt][kc][h2 * 2 + 0] = pack_hi(dv[0], dv[1]);
                alo[mt][kc][h2 * 2 + 0] = pack_lo(dv[0], dv[1]);
                ahi[mt][kc][h2 * 2 + 1] = pack_hi(dv[2], dv[3]);
                alo[mt][kc][h2 * 2 + 1] = pack_lo(dv[2], dv[3]);
            }
        }
    }

    // ---- GEMM2: out = W2 . x_deform ----
    #pragma unroll
    for (int mt = 0; mt < 2; mt++)
        #pragma unroll
        for (int nt = 0; nt < 8; nt++)
            #pragma unroll
            for (int j = 0; j < 4; j++) acc[mt][nt][j] = 0.f;

    RUN_GEMM(g_Bf2);

    // ---- epilogue: bias + scattered-but-sectored STG.32 ----
    const float2* b2p = reinterpret_cast<const float2*>(b2v);
    float* ob = out + (size_t)b * (size_t)(C_ * L_) + l0;
    #pragma unroll
    for (int nt = 0; nt < 8; nt++) {
        const float2 bias = __ldg(b2p + nt * 4 + q);
        const int ch0 = nt * 8 + 2 * q;
        float* row0 = ob + (size_t)ch0 * L_;
        float* row1 = row0 + L_;
        #pragma unroll
        for (int mt = 0; mt < 2; mt++) {
            const int p0 = r + 16 * mt;
            row0[p0]     = acc[mt][nt][0] + bias.x;
            row1[p0]     = acc[mt][nt][1] + bias.y;
            row0[p0 + 8] = acc[mt][nt][2] + bias.x;
            row1[p0 + 8] = acc[mt][nt][3] + bias.y;
        }
    }
}

extern "C" void kernel_launch(void* const* d_in, const int* in_sizes, int n_in,
                              void* d_out, int out_size)
{
    (void)in_sizes; (void)n_in; (void)out_size;
    const float* x  = (const float*)d_in[0];
    const float* w1 = (const float*)d_in[1];
    const float* b1 = (const float*)d_in[2];
    const float* w2 = (const float*)d_in[3];
    const float* b2 = (const float*)d_in[4];
    float* out = (float*)d_out;

    build_frags_kernel<<<8, 256>>>(w1, w2);

    dim3 grid(L_ / T_, B_);
    deform_conv1d_kernel<<<grid, NT>>>(x, b1, b2, out);
}

// round 12
// speedup vs baseline: 2.9051x; 1.1441x over previous
#include <cuda_runtime.h>
#include <cuda_bf16.h>
#include <cstdint>

#define B_  32
#define C_  64
#define L_  16384
#define T_  128
#define NT  128
#define H_  16
#define SXP 164     // haloed row stride: 164 mod 32 = 4 -> column LDS conflict-free

// Precomputed B fragments (weights in exact mma.sync B-fragment layout).
// [kcD(8: 0-3 = w_hi chunks, 4-7 = w_lo chunks)][nt(8)][lane(32)] -> uint2 {b0,b1}
__device__ __align__(16) uint2 g_Bf1[8 * 8 * 32];
__device__ __align__(16) uint2 g_Bf2[8 * 8 * 32];

// ---- bf16 split helpers: hi = truncation (prmt), lo = rn(f - hi) ----
__device__ __forceinline__ uint32_t pack_hi(float f0, float f1) {
    uint32_t r;
    asm("prmt.b32 %0, %1, %2, 0x7632;"
        : "=r"(r) : "r"(__float_as_uint(f0)), "r"(__float_as_uint(f1)));
    return r;                     // {lo16 = hi16(f0), hi16 = hi16(f1)}
}
__device__ __forceinline__ uint32_t pack_lo(float f0, float f1) {
    float h0 = __uint_as_float(__float_as_uint(f0) & 0xFFFF0000u);
    float h1 = __uint_as_float(__float_as_uint(f1) & 0xFFFF0000u);
    float l0 = f0 - h0, l1 = f1 - h1;
    uint32_t d;
    asm("cvt.rn.bf16x2.f32 %0, %1, %2;" : "=r"(d) : "f"(l1), "f"(l0));
    return d;                     // {lo16 = bf16(l0), hi16 = bf16(l1)}
}

// ---- prologue: build B fragments for both weight matrices ----
__global__ void build_frags_kernel(const float* __restrict__ w1,
                                   const float* __restrict__ w2)
{
    int i = blockIdx.x * blockDim.x + threadIdx.x;
    if (i >= 8 * 8 * 32) return;
    int lane = i & 31, nt = (i >> 5) & 7, kcD = i >> 8;
    int q = lane & 3, trow = lane >> 2;
    int co = nt * 8 + trow;
    int cb = (kcD & 3) * 16 + 2 * q;
    bool lo = (kcD >= 4);

    float f0 = w1[co * 64 + cb],     f1 = w1[co * 64 + cb + 1];
    float f2 = w1[co * 64 + cb + 8], f3 = w1[co * 64 + cb + 9];
    g_Bf1[i] = lo ? make_uint2(pack_lo(f0, f1), pack_lo(f2, f3))
                  : make_uint2(pack_hi(f0, f1), pack_hi(f2, f3));

    f0 = w2[co * 64 + cb];     f1 = w2[co * 64 + cb + 1];
    f2 = w2[co * 64 + cb + 8]; f3 = w2[co * 64 + cb + 9];
    g_Bf2[i] = lo ? make_uint2(pack_lo(f0, f1), pack_lo(f2, f3))
                  : make_uint2(pack_hi(f0, f1), pack_hi(f2, f3));
}

#define MMA16816(c, a, b0, b1)                                                 \
    asm volatile("mma.sync.aligned.m16n8k16.row.col.f32.bf16.bf16.f32 "        \
        "{%0,%1,%2,%3}, {%4,%5,%6,%7}, {%8,%9}, {%0,%1,%2,%3};"                \
        : "+f"((c)[0]), "+f"((c)[1]), "+f"((c)[2]), "+f"((c)[3])               \
        : "r"((a)[0]), "r"((a)[1]), "r"((a)[2]), "r"((a)[3]),                  \
          "r"(b0), "r"(b1))

// 6 MMAs for one K-chunk: hi.bhi + lo.bhi + hi.blo, both m-tiles.
#define CHUNK_MMAS(ACC, AH, AL, BPH, BPL)                                      \
    _Pragma("unroll")                                                          \
    for (int nt = 0; nt < 8; nt++) {                                           \
        uint2 bh = __ldg((BPH) + nt * 32);                                     \
        uint2 bl = __ldg((BPL) + nt * 32);                                     \
        MMA16816((ACC)[0][nt], (AH)[0], bh.x, bh.y);                           \
        MMA16816((ACC)[1][nt], (AH)[1], bh.x, bh.y);                           \
        MMA16816((ACC)[0][nt], (AL)[0], bh.x, bh.y);                           \
        MMA16816((ACC)[1][nt], (AL)[1], bh.x, bh.y);                           \
        MMA16816((ACC)[0][nt], (AH)[0], bl.x, bl.y);                           \
        MMA16816((ACC)[1][nt], (AH)[1], bl.x, bl.y);                           \
    }

__global__ void __launch_bounds__(NT, 3)
deform_conv1d_kernel(const float* __restrict__ x,
                     const float* __restrict__ b1v,
                     const float* __restrict__ b2v,
                     float* __restrict__ out)
{
    __shared__ __align__(16) float s_xh[C_ * SXP];   // 41984 B

    const int b   = blockIdx.y;
    const int l0  = blockIdx.x * T_;
    const int tid = threadIdx.x;
    const float* xb = x + (size_t)b * (size_t)(C_ * L_);

    // ---- haloed x tile [64][164] covering [l0-16, l0+148) ----
    if (blockIdx.x != 0 && blockIdx.x != gridDim.x - 1) {
        #pragma unroll 4
        for (int i = tid; i < C_ * (SXP / 4); i += NT) {
            int c = i / (SXP / 4), j = i - c * (SXP / 4);
            float4 v = *reinterpret_cast<const float4*>(
                xb + (size_t)c * L_ + (l0 - H_) + (j << 2));
            *reinterpret_cast<float4*>(&s_xh[c * SXP + (j << 2)]) = v;
        }
    } else {
        for (int i = tid; i < C_ * SXP; i += NT) {
            int c = i / SXP, j = i - c * SXP;
            int g = min(max(l0 - H_ + j, 0), L_ - 1);
            s_xh[c * SXP + j] = xb[(size_t)c * L_ + g];
        }
    }
    __syncthreads();        // the only block-wide sync

    const int lane = tid & 31, warp = tid >> 5;
    const int q = lane & 3, trow = lane >> 2;
    const int r = warp * 32 + trow;     // base tile row; thread rows r+{0,8,16,24}

    // ---- GEMM1: acc1 initialized with b1 bias, per-kc A build + MMAs ----
    const float2* b1p = reinterpret_cast<const float2*>(b1v);
    float acc1[2][8][4];
    #pragma unroll
    for (int nt = 0; nt < 8; nt++) {
        float2 bv = __ldg(b1p + nt * 4 + q);
        #pragma unroll
        for (int mt = 0; mt < 2; mt++) {
            acc1[mt][nt][0] = bv.x; acc1[mt][nt][1] = bv.y;
            acc1[mt][nt][2] = bv.x; acc1[mt][nt][3] = bv.y;
        }
    }

    #pragma unroll
    for (int kc = 0; kc < 4; kc++) {
        uint32_t ah[2][4], al[2][4];    // A frags for THIS chunk only (16 regs)
        #pragma unroll
        for (int pi = 0; pi < 4; pi++) {
            const int p  = r + 8 * pi + H_;
            const int mt = pi >> 1, jr = pi & 1;
            const int cb = kc * 16 + 2 * q;
            float f0 = s_xh[cb * SXP + p],       f1 = s_xh[(cb + 1) * SXP + p];
            float f2 = s_xh[(cb + 8) * SXP + p], f3 = s_xh[(cb + 9) * SXP + p];
            ah[mt][jr]     = pack_hi(f0, f1);  al[mt][jr]     = pack_lo(f0, f1);
            ah[mt][2 + jr] = pack_hi(f2, f3);  al[mt][2 + jr] = pack_lo(f2, f3);
        }
        const uint2* bph = g_Bf1 + kc * 256 + lane;
        const uint2* bpl = g_Bf1 + (kc + 4) * 256 + lane;
        CHUNK_MMAS(acc1, ah, al, bph, bpl);
    }

    // ---- GEMM2: acc2 initialized with b2 bias; gather feeds A per-kc ----
    const float2* b2p = reinterpret_cast<const float2*>(b2v);
    float acc2[2][8][4];
    #pragma unroll
    for (int nt = 0; nt < 8; nt++) {
        float2 bv = __ldg(b2p + nt * 4 + q);
        #pragma unroll
        for (int mt = 0; mt < 2; mt++) {
            acc2[mt][nt][0] = bv.x; acc2[mt][nt][1] = bv.y;
            acc2[mt][nt][2] = bv.x; acc2[mt][nt][3] = bv.y;
        }
    }

    #pragma unroll
    for (int kc = 0; kc < 4; kc++) {
        uint32_t ah[2][4], al[2][4];
        // gather channels [16kc, 16kc+16) -> A2 fragments (offsets = acc1, bias folded)
        #pragma unroll
        for (int mt = 0; mt < 2; mt++) {
            const int p0 = l0 + r + 16 * mt;
            #pragma unroll
            for (int h2 = 0; h2 < 2; h2++) {
                const int nt  = 2 * kc + h2;
                const int ch0 = nt * 8 + 2 * q;
                float dv[4];
                #pragma unroll
                for (int e = 0; e < 4; e++) {   // e: {row0,c0},{row0,c1},{row1,c0},{row1,c1}
                    const int   ch   = ch0 + (e & 1);
                    const int   gpos = p0 + (e >> 1) * 8;
                    const float off  = acc1[mt][nt][e];
                    float posf = fminf(fmaxf((float)gpos + off, 0.0f), (float)(L_ - 1));
                    float fl   = floorf(posf);
                    float fr   = posf - fl;
                    int   i0   = (int)fl;
                    int   h    = i0 - l0 + H_;
                    float v0, v1;
                    if ((unsigned)h <= (unsigned)(SXP - 2)) {
                        v0 = s_xh[ch * SXP + h];
                        v1 = s_xh[ch * SXP + h + 1];
                    } else {                     // rare out-of-halo fallback
                        const float* rowp = xb + (size_t)ch * L_;
                        v0 = __ldg(rowp + i0);
                        v1 = __ldg(rowp + min(i0 + 1, L_ - 1));
                    }
                    dv[e] = fmaf(fr, v1 - v0, v0);
                }
                ah[mt][h2 * 2 + 0] = pack_hi(dv[0], dv[1]);
                al[mt][h2 * 2 + 0] = pack_lo(dv[0], dv[1]);
                ah[mt][h2 * 2 + 1] = pack_hi(dv[2], dv[3]);
                al[mt][h2 * 2 + 1] = pack_lo(dv[2], dv[3]);
            }
        }
        const uint2* bph = g_Bf2 + kc * 256 + lane;
        const uint2* bpl = g_Bf2 + (kc + 4) * 256 + lane;
        CHUNK_MMAS(acc2, ah, al, bph, bpl);
    }

    // ---- epilogue: bias already folded; sectored STG.32 ----
    float* ob = out + (size_t)b * (size_t)(C_ * L_) + l0;
    #pragma unroll
    for (int nt = 0; nt < 8; nt++) {
        const int ch0 = nt * 8 + 2 * q;
        float* row0 = ob + (size_t)ch0 * L_;
        float* row1 = row0 + L_;
        #pragma unroll
        for (int mt = 0; mt < 2; mt++) {
            const int p0 = r + 16 * mt;
            row0[p0]     = acc2[mt][nt][0];
            row1[p0]     = acc2[mt][nt][1];
            row0[p0 + 8] = acc2[mt][nt][2];
            row1[p0 + 8] = acc2[mt][nt][3];
        }
    }
}

extern "C" void kernel_launch(void* const* d_in, const int* in_sizes, int n_in,
                              void* d_out, int out_size)
{
    (void)in_sizes; (void)n_in; (void)out_size;
    const float* x  = (const float*)d_in[0];
    const float* w1 = (const float*)d_in[1];
    const float* b1 = (const float*)d_in[2];
    const float* w2 = (const float*)d_in[3];
    const float* b2 = (const float*)d_in[4];
    float* out = (float*)d_out;

    build_frags_kernel<<<8, 256>>>(w1, w2);

    dim3 grid(L_ / T_, B_);
    deform_conv1d_kernel<<<grid, NT>>>(x, b1, b2, out);
}